// round 5
// baseline (speedup 1.0000x reference)
#include <cuda_runtime.h>
#include <cstdint>
#include <math_constants.h>

#define TOKENS  16384      // B*S
#define HDIM    4096
#define NEXP    64
#define MT      128        // tokens per CTA
#define KB      32         // k per stage
#define NST     (HDIM / KB)
#define NK8     (KB / 8)
#define NTHREADS 256       // 8 warps: 4 m-groups x 2 n-groups

// per-buffer smem layout (bytes), fragment-ordered tf32 hi/lo
#define AHI_OFF 0          // [8 mtiles][4 k8][32 lanes][4 regs] f32 = 16KB
#define ALO_OFF 16384
#define BHI_OFF 32768      // [8 ntiles][4 k8][32 lanes][2 regs] = 8KB
#define BLO_OFF 40960
#define BUF_BYTES 49152
#define SMEM_TOTAL (2 * BUF_BYTES)   // 96KB

__device__ __forceinline__ void split_tf32(float v, uint32_t& hi, uint32_t& lo) {
    asm("cvt.rna.tf32.f32 %0, %1;" : "=r"(hi) : "f"(v));
    float l = v - __uint_as_float(hi);
    asm("cvt.rna.tf32.f32 %0, %1;" : "=r"(lo) : "f"(l));
}

__device__ __forceinline__ void mma_tf32(float* d, const uint32_t* a, const uint32_t* b) {
    asm volatile(
        "mma.sync.aligned.m16n8k8.row.col.f32.tf32.tf32.f32 "
        "{%0,%1,%2,%3}, {%4,%5,%6,%7}, {%8,%9}, {%0,%1,%2,%3};"
        : "+f"(d[0]), "+f"(d[1]), "+f"(d[2]), "+f"(d[3])
        : "r"(a[0]), "r"(a[1]), "r"(a[2]), "r"(a[3]), "r"(b[0]), "r"(b[1]));
}

__global__ __launch_bounds__(NTHREADS, 1)
void molora_router_mma(const float* __restrict__ x,
                       const float* __restrict__ w,
                       float* __restrict__ out)
{
    extern __shared__ char smem[];
    const int tid  = threadIdx.x;
    const int wid  = tid >> 5;
    const int lane = tid & 31;
    const int wm   = wid & 3;   // m-group: handles m-tiles {2wm, 2wm+1}
    const int wn   = wid >> 2;  // n-group: handles n-tiles {4wn..4wn+3} (experts wn*32 .. +31)
    const int m0   = blockIdx.x * MT;

    float d[2][4][4];
#pragma unroll
    for (int mi = 0; mi < 2; mi++)
#pragma unroll
        for (int ni = 0; ni < 4; ni++)
#pragma unroll
            for (int r = 0; r < 4; r++) d[mi][ni][r] = 0.0f;

    // prefetch registers
    float4 pa[4], pb[2];

    auto load_g = [&](int s) {
        const int k0 = s * KB;
#pragma unroll
        for (int p = 0; p < 4; p++) {
            int q = tid + NTHREADS * p;
            pa[p] = *(const float4*)(x + (size_t)(m0 + (q >> 3)) * HDIM + k0 + (q & 7) * 4);
        }
#pragma unroll
        for (int p = 0; p < 2; p++) {
            int q = tid + NTHREADS * p;
            pb[p] = *(const float4*)(w + (size_t)(q >> 3) * HDIM + k0 + (q & 7) * 4);
        }
    };

    auto store_s = [&](int buf) {
        char* base = smem + buf * BUF_BYTES;
        // A: fragment order  (token,k) -> [mt][k8][lane][reg]
#pragma unroll
        for (int p = 0; p < 4; p++) {
            int q = tid + NTHREADS * p;
            int token = q >> 3, kq = q & 7;
#pragma unroll
            for (int j = 0; j < 4; j++) {
                float f = (&pa[p].x)[j];
                uint32_t hi, lo;
                split_tf32(f, hi, lo);
                int k  = kq * 4 + j;
                int mt = token >> 4, r = token & 15, k8 = k >> 3, kk = k & 7;
                int fl  = ((r & 7) << 2) + (kk & 3);
                int reg = ((kk >> 2) << 1) + (r >> 3);
                int off = ((((mt << 2) + k8) * 32 + fl) * 4 + reg) * 4;
                *(uint32_t*)(base + AHI_OFF + off) = hi;
                *(uint32_t*)(base + ALO_OFF + off) = lo;
            }
        }
        // B: (exp,k) -> [nt][k8][lane][reg]
#pragma unroll
        for (int p = 0; p < 2; p++) {
            int q = tid + NTHREADS * p;
            int exp = q >> 3, kq = q & 7;
#pragma unroll
            for (int j = 0; j < 4; j++) {
                float f = (&pb[p].x)[j];
                uint32_t hi, lo;
                split_tf32(f, hi, lo);
                int k  = kq * 4 + j;
                int nt = exp >> 3, nr = exp & 7, k8 = k >> 3, kk = k & 7;
                int fl  = (nr << 2) + (kk & 3);
                int reg = kk >> 2;
                int off = ((((nt << 2) + k8) * 32 + fl) * 2 + reg) * 4;
                *(uint32_t*)(base + BHI_OFF + off) = hi;
                *(uint32_t*)(base + BLO_OFF + off) = lo;
            }
        }
    };

    // prologue
    load_g(0);
    store_s(0);
    __syncthreads();

    for (int s = 0; s < NST; s++) {
        const int cur = s & 1;
        const bool has_next = (s + 1 < NST);
        if (has_next) load_g(s + 1);

        const char* base = smem + cur * BUF_BYTES;
#pragma unroll
        for (int k8 = 0; k8 < NK8; k8++) {
            uint4 ahi[2], alo[2];
#pragma unroll
            for (int mi = 0; mi < 2; mi++) {
                int mt  = wm * 2 + mi;
                int off = (((mt << 2) + k8) * 32 + lane) * 16;
                ahi[mi] = *(const uint4*)(base + AHI_OFF + off);
                alo[mi] = *(const uint4*)(base + ALO_OFF + off);
            }
            uint2 bhi[4], blo[4];
#pragma unroll
            for (int ni = 0; ni < 4; ni++) {
                int nt  = wn * 4 + ni;
                int off = (((nt << 2) + k8) * 32 + lane) * 8;
                bhi[ni] = *(const uint2*)(base + BHI_OFF + off);
                blo[ni] = *(const uint2*)(base + BLO_OFF + off);
            }
#pragma unroll
            for (int mi = 0; mi < 2; mi++)
#pragma unroll
                for (int ni = 0; ni < 4; ni++) {
                    mma_tf32(d[mi][ni], (const uint32_t*)&ahi[mi], (const uint32_t*)&bhi[ni]);
                    mma_tf32(d[mi][ni], (const uint32_t*)&ahi[mi], (const uint32_t*)&blo[ni]);
                    mma_tf32(d[mi][ni], (const uint32_t*)&alo[mi], (const uint32_t*)&bhi[ni]);
                }
        }

        if (has_next) store_s(cur ^ 1);
        __syncthreads();
    }

    // ---- epilogue: per-warp top-2 over its 32 experts, then cross-half merge ----
    // candidate buffer reuses stage smem: red[token][half] = {v1, v2, i1, i2}
    float4* red = (float4*)smem;   // 128 * 2 * 16B = 4KB

#pragma unroll
    for (int mi = 0; mi < 2; mi++) {
#pragma unroll
        for (int h = 0; h < 2; h++) {   // h=0: row = lane>>2, h=1: row+8
            float v1 = -CUDART_INF_F, v2 = -CUDART_INF_F;
            int i1 = 0, i2 = 0;
#pragma unroll
            for (int ni = 0; ni < 4; ni++)
#pragma unroll
                for (int r = 0; r < 2; r++) {
                    float v = d[mi][ni][h * 2 + r];
                    int   e = (wn * 4 + ni) * 8 + (lane & 3) * 2 + r;
                    if (v > v1)      { v2 = v1; i2 = i1; v1 = v; i1 = e; }
                    else if (v > v2) { v2 = v;  i2 = e; }
                }
            // reduce across the 4 lanes of the quad (same token)
#pragma unroll
            for (int mk = 1; mk <= 2; mk <<= 1) {
                float ov1 = __shfl_xor_sync(0xffffffffu, v1, mk);
                float ov2 = __shfl_xor_sync(0xffffffffu, v2, mk);
                int   oi1 = __shfl_xor_sync(0xffffffffu, i1, mk);
                int   oi2 = __shfl_xor_sync(0xffffffffu, i2, mk);
                bool o1_beats_m1 = (ov1 > v1) || (ov1 == v1 && oi1 < i1);
                if (o1_beats_m1) {
                    bool m1_beats_o2 = (v1 > ov2) || (v1 == ov2 && i1 < oi2);
                    v2 = m1_beats_o2 ? v1 : ov2;
                    i2 = m1_beats_o2 ? i1 : oi2;
                    v1 = ov1; i1 = oi1;
                } else {
                    bool o1_beats_m2 = (ov1 > v2) || (ov1 == v2 && oi1 < i2);
                    if (o1_beats_m2) { v2 = ov1; i2 = oi1; }
                }
            }
            if ((lane & 3) == 0) {
                int tok = (wm * 2 + mi) * 16 + (lane >> 2) + h * 8;  // 0..127 in CTA
                red[tok * 2 + wn] = make_float4(v1, v2, (float)i1, (float)i2);
            }
        }
    }
    __syncthreads();

    if (tid < MT) {
        float4 a = red[tid * 2 + 0];   // experts 0..31  (smaller indices)
        float4 b = red[tid * 2 + 1];   // experts 32..63
        float v1, v2; int i1, i2;
        // merge two descending pairs; ties prefer half 0 (smaller index), per lax.top_k
        if (a.x >= b.x) {
            v1 = a.x; i1 = (int)a.z;
            if (a.y >= b.x) { v2 = a.y; i2 = (int)a.w; }
            else            { v2 = b.x; i2 = (int)b.z; }
        } else {
            v1 = b.x; i1 = (int)b.z;
            if (a.x >= b.y) { v2 = a.x; i2 = (int)a.z; }
            else            { v2 = b.y; i2 = (int)b.w; }
        }
        float sfx = expf(v2 - v1);       // <= 1
        float inv = 1.0f / (1.0f + sfx);
        const int gt = m0 + tid;
        out[2 * gt + 0] = inv;
        out[2 * gt + 1] = sfx * inv;
        out[(size_t)TOKENS * 2 + 2 * gt + 0] = (float)i1;
        out[(size_t)TOKENS * 2 + 2 * gt + 1] = (float)i2;
    }
}

extern "C" void kernel_launch(void* const* d_in, const int* in_sizes, int n_in,
                              void* d_out, int out_size)
{
    const float* x = (const float*)d_in[0];      // [4,4096,4096] f32
    const float* w = (const float*)d_in[1];      // [64,4096]     f32
    float* out = (float*)d_out;

    (void)in_sizes; (void)n_in; (void)out_size;

    cudaFuncSetAttribute(molora_router_mma,
                         cudaFuncAttributeMaxDynamicSharedMemorySize, SMEM_TOTAL);

    dim3 grid(TOKENS / MT);   // 128 CTAs
    dim3 block(NTHREADS);
    molora_router_mma<<<grid, block, SMEM_TOTAL>>>(x, w, out);
}

// round 6
// speedup vs baseline: 1.4837x; 1.4837x over previous
#include <cuda_runtime.h>
#include <cstdint>
#include <math_constants.h>

#define TOKENS  16384      // B*S
#define HDIM    4096
#define NEXP    64
#define MT      128        // tokens per CTA
#define KB      32         // k per stage
#define NST     (HDIM / KB)
#define NTHREADS 256       // 8 warps: 4 m-groups x 2 n-groups

#define A_STRIDE 36                       // floats per row (pad: 36 mod 32 = 4 -> conflict-free)
#define A_BYTES  (MT * A_STRIDE * 4)      // 18432
#define B_BYTES  (NEXP * A_STRIDE * 4)    // 9216
#define STG_BYTES (A_BYTES + B_BYTES)     // 27648
#define NBUF 3
#define SMEM_TOTAL (NBUF * STG_BYTES)     // 82944

__device__ __forceinline__ void cp_async16(void* sdst, const void* gsrc) {
    uint32_t s = (uint32_t)__cvta_generic_to_shared(sdst);
    asm volatile("cp.async.cg.shared.global [%0], [%1], 16;\n"
                 :: "r"(s), "l"(gsrc) : "memory");
}
__device__ __forceinline__ void cp_commit() {
    asm volatile("cp.async.commit_group;\n" ::: "memory");
}
template <int N>
__device__ __forceinline__ void cp_wait() {
    asm volatile("cp.async.wait_group %0;\n" :: "n"(N) : "memory");
}

__device__ __forceinline__ void split_tf32(float v, uint32_t& hi, uint32_t& lo) {
    asm("cvt.rna.tf32.f32 %0, %1;" : "=r"(hi) : "f"(v));
    float l = v - __uint_as_float(hi);
    asm("cvt.rna.tf32.f32 %0, %1;" : "=r"(lo) : "f"(l));
}

__device__ __forceinline__ void mma_tf32(float* d, const uint32_t* a, const uint32_t* b) {
    asm volatile(
        "mma.sync.aligned.m16n8k8.row.col.f32.tf32.tf32.f32 "
        "{%0,%1,%2,%3}, {%4,%5,%6,%7}, {%8,%9}, {%0,%1,%2,%3};"
        : "+f"(d[0]), "+f"(d[1]), "+f"(d[2]), "+f"(d[3])
        : "r"(a[0]), "r"(a[1]), "r"(a[2]), "r"(a[3]), "r"(b[0]), "r"(b[1]));
}

__global__ __launch_bounds__(NTHREADS, 1)
void molora_router_mma(const float* __restrict__ x,
                       const float* __restrict__ w,
                       float* __restrict__ out)
{
    extern __shared__ char smem[];
    const int tid  = threadIdx.x;
    const int wid  = tid >> 5;
    const int lane = tid & 31;
    const int wm   = wid & 3;   // m-group: m-tiles {2wm, 2wm+1}
    const int wn   = wid >> 2;  // n-group: experts wn*32 .. +31
    const int m0   = blockIdx.x * MT;

    const int row = lane >> 2;     // fragment row / n-index
    const int qk  = lane & 3;      // fragment k within half

    float d[2][4][4];
#pragma unroll
    for (int mi = 0; mi < 2; mi++)
#pragma unroll
        for (int ni = 0; ni < 4; ni++)
#pragma unroll
            for (int r = 0; r < 4; r++) d[mi][ni][r] = 0.0f;

    // ---- async fill of stage s into buffer buf ----
    auto fill = [&](int s, int buf) {
        char* Ab = smem + buf * STG_BYTES;
        char* Bb = Ab + A_BYTES;
        const int k0 = s * KB;
#pragma unroll
        for (int p = 0; p < 4; p++) {
            int q = tid + NTHREADS * p;
            int token = q >> 3, kq = q & 7;
            cp_async16(Ab + token * (A_STRIDE * 4) + kq * 16,
                       x + (size_t)(m0 + token) * HDIM + k0 + kq * 4);
        }
#pragma unroll
        for (int p = 0; p < 2; p++) {
            int q = tid + NTHREADS * p;
            int exp = q >> 3, kq = q & 7;
            cp_async16(Bb + exp * (A_STRIDE * 4) + kq * 16,
                       w + (size_t)exp * HDIM + k0 + kq * 4);
        }
        cp_commit();
    };

    // prologue: two stages in flight
    fill(0, 0);
    fill(1, 1);

    for (int s = 0; s < NST; s++) {
        const int buf = s % NBUF;
        if (s + 1 < NST) cp_wait<1>();   // stage s complete, s+1 may pend
        else             cp_wait<0>();
        __syncthreads();

        const float* Af = (const float*)(smem + buf * STG_BYTES);
        const float* Bf = Af + MT * A_STRIDE;

#pragma unroll
        for (int k8 = 0; k8 < 4; k8++) {
            const int col = k8 * 8 + qk;
            uint32_t ahi[2][4], alo[2][4];
#pragma unroll
            for (int mi = 0; mi < 2; mi++) {
                const int tb = (wm * 2 + mi) * 16 + row;
                float f0 = Af[tb * A_STRIDE + col];
                float f1 = Af[(tb + 8) * A_STRIDE + col];
                float f2 = Af[tb * A_STRIDE + col + 4];
                float f3 = Af[(tb + 8) * A_STRIDE + col + 4];
                split_tf32(f0, ahi[mi][0], alo[mi][0]);
                split_tf32(f1, ahi[mi][1], alo[mi][1]);
                split_tf32(f2, ahi[mi][2], alo[mi][2]);
                split_tf32(f3, ahi[mi][3], alo[mi][3]);
            }
            uint32_t bhi[4][2], blo[4][2];
#pragma unroll
            for (int ni = 0; ni < 4; ni++) {
                const int eb = (wn * 4 + ni) * 8 + row;
                float g0 = Bf[eb * A_STRIDE + col];
                float g1 = Bf[eb * A_STRIDE + col + 4];
                split_tf32(g0, bhi[ni][0], blo[ni][0]);
                split_tf32(g1, bhi[ni][1], blo[ni][1]);
            }
#pragma unroll
            for (int mi = 0; mi < 2; mi++)
#pragma unroll
                for (int ni = 0; ni < 4; ni++) {
                    mma_tf32(d[mi][ni], ahi[mi], bhi[ni]);
                    mma_tf32(d[mi][ni], ahi[mi], blo[ni]);
                    mma_tf32(d[mi][ni], alo[mi], bhi[ni]);
                }
        }

        __syncthreads();                 // everyone done reading buf
        if (s + 2 < NST) fill(s + 2, (s + 2) % NBUF);
    }

    // ---- epilogue: per-warp top-2 over its 32 experts, then cross-half merge ----
    float4* red = (float4*)smem;   // 128 tokens x 2 halves x 16B = 4KB (buffers dead)

#pragma unroll
    for (int mi = 0; mi < 2; mi++) {
#pragma unroll
        for (int h = 0; h < 2; h++) {   // h=0: row, h=1: row+8
            float v1 = -CUDART_INF_F, v2 = -CUDART_INF_F;
            int i1 = 0, i2 = 0;
#pragma unroll
            for (int ni = 0; ni < 4; ni++)
#pragma unroll
                for (int r = 0; r < 2; r++) {
                    float v = d[mi][ni][h * 2 + r];
                    int   e = (wn * 4 + ni) * 8 + qk * 2 + r;
                    if (v > v1)      { v2 = v1; i2 = i1; v1 = v; i1 = e; }
                    else if (v > v2) { v2 = v;  i2 = e; }
                }
#pragma unroll
            for (int mk = 1; mk <= 2; mk <<= 1) {
                float ov1 = __shfl_xor_sync(0xffffffffu, v1, mk);
                float ov2 = __shfl_xor_sync(0xffffffffu, v2, mk);
                int   oi1 = __shfl_xor_sync(0xffffffffu, i1, mk);
                int   oi2 = __shfl_xor_sync(0xffffffffu, i2, mk);
                bool o1_beats_m1 = (ov1 > v1) || (ov1 == v1 && oi1 < i1);
                if (o1_beats_m1) {
                    bool m1_beats_o2 = (v1 > ov2) || (v1 == ov2 && i1 < oi2);
                    v2 = m1_beats_o2 ? v1 : ov2;
                    i2 = m1_beats_o2 ? i1 : oi2;
                    v1 = ov1; i1 = oi1;
                } else {
                    bool o1_beats_m2 = (ov1 > v2) || (ov1 == v2 && oi1 < i2);
                    if (o1_beats_m2) { v2 = ov1; i2 = oi1; }
                }
            }
            if (qk == 0) {
                int tok = (wm * 2 + mi) * 16 + row + h * 8;   // 0..127
                red[tok * 2 + wn] = make_float4(v1, v2, (float)i1, (float)i2);
            }
        }
    }
    __syncthreads();

    if (tid < MT) {
        float4 a = red[tid * 2 + 0];   // experts 0..31 (smaller indices)
        float4 b = red[tid * 2 + 1];   // experts 32..63
        float v1, v2; int i1, i2;
        if (a.x >= b.x) {
            v1 = a.x; i1 = (int)a.z;
            if (a.y >= b.x) { v2 = a.y; i2 = (int)a.w; }
            else            { v2 = b.x; i2 = (int)b.z; }
        } else {
            v1 = b.x; i1 = (int)b.z;
            if (a.x >= b.y) { v2 = a.x; i2 = (int)a.z; }
            else            { v2 = b.y; i2 = (int)b.w; }
        }
        float sfx = expf(v2 - v1);       // <= 1
        float inv = 1.0f / (1.0f + sfx);
        const int gt = m0 + tid;
        out[2 * gt + 0] = inv;
        out[2 * gt + 1] = sfx * inv;
        out[(size_t)TOKENS * 2 + 2 * gt + 0] = (float)i1;
        out[(size_t)TOKENS * 2 + 2 * gt + 1] = (float)i2;
    }
}

extern "C" void kernel_launch(void* const* d_in, const int* in_sizes, int n_in,
                              void* d_out, int out_size)
{
    const float* x = (const float*)d_in[0];      // [4,4096,4096] f32
    const float* w = (const float*)d_in[1];      // [64,4096]     f32
    float* out = (float*)d_out;

    (void)in_sizes; (void)n_in; (void)out_size;

    cudaFuncSetAttribute(molora_router_mma,
                         cudaFuncAttributeMaxDynamicSharedMemorySize, SMEM_TOTAL);

    dim3 grid(TOKENS / MT);   // 128 CTAs
    dim3 block(NTHREADS);
    molora_router_mma<<<grid, block, SMEM_TOTAL>>>(x, w, out);
}